// round 1
// baseline (speedup 1.0000x reference)
#include <cuda_runtime.h>
#include <math.h>

#define BATCH 4096

// ---------------- scratch (no allocations allowed) ----------------
__device__ float g_h1[BATCH * 1024];
__device__ float g_h2[BATCH * 512];
__device__ float g_enc[BATCH * 256];
__device__ float g_meas[BATCH * 24];
__device__ float g_d1[BATCH * 128];
__device__ float g_d2[BATCH * 256];
__device__ float g_d3[BATCH * 512];
__device__ float g_d4[BATCH * 1024];

// ---------------- fused SGEMM: C = act(A @ W + bias) ----------------
// A: (M,K) row-major, W: (K,N) row-major, bias: (N), C: (M,N)
// Requires: M % 128 == 0, N % 128 == 0, K % 8 == 0 (true for every layer here)
// ACT: 0 = none, 1 = leaky(0.2), 2 = tanh

template <int ACT>
__device__ __forceinline__ float activate(float x) {
    if (ACT == 1) return x >= 0.0f ? x : 0.2f * x;
    if (ACT == 2) return tanhf(x);
    return x;
}

template <int ACT>
__global__ void __launch_bounds__(256)
sgemm_bias_act(const float* __restrict__ A, const float* __restrict__ W,
               const float* __restrict__ bias, float* __restrict__ C,
               int M, int N, int K) {
    constexpr int BM = 128, BN = 128, BK = 8;
    __shared__ float As[BK][BM];   // A tile, transposed for coalesced frag reads
    __shared__ float Ws[BK][BN];

    const int tid = threadIdx.x;
    const int tx = tid & 15;   // 16 col groups of 8
    const int ty = tid >> 4;   // 16 row groups of 8
    const int row0 = blockIdx.y * BM;
    const int col0 = blockIdx.x * BN;

    // A-tile load mapping: 2 threads per row, one float4 each (K%8==0 -> aligned)
    const int a_row = tid >> 1;            // 0..127
    const int a_col = (tid & 1) << 2;      // 0 or 4
    // W-tile load mapping: 32 threads per row of 128, one float4 each
    const int w_row = tid >> 5;            // 0..7
    const int w_col = (tid & 31) << 2;     // 0..124

    float acc[8][8];
#pragma unroll
    for (int i = 0; i < 8; i++)
#pragma unroll
        for (int j = 0; j < 8; j++) acc[i][j] = 0.0f;

    for (int k0 = 0; k0 < K; k0 += BK) {
        float4 av = *reinterpret_cast<const float4*>(
            &A[(size_t)(row0 + a_row) * K + k0 + a_col]);
        As[a_col + 0][a_row] = av.x;
        As[a_col + 1][a_row] = av.y;
        As[a_col + 2][a_row] = av.z;
        As[a_col + 3][a_row] = av.w;

        float4 wv = *reinterpret_cast<const float4*>(
            &W[(size_t)(k0 + w_row) * N + col0 + w_col]);
        *reinterpret_cast<float4*>(&Ws[w_row][w_col]) = wv;

        __syncthreads();

#pragma unroll
        for (int k = 0; k < BK; k++) {
            float af[8], wf[8];
            float4 a0 = *reinterpret_cast<const float4*>(&As[k][ty * 8]);
            float4 a1 = *reinterpret_cast<const float4*>(&As[k][ty * 8 + 4]);
            float4 w0 = *reinterpret_cast<const float4*>(&Ws[k][tx * 8]);
            float4 w1 = *reinterpret_cast<const float4*>(&Ws[k][tx * 8 + 4]);
            af[0] = a0.x; af[1] = a0.y; af[2] = a0.z; af[3] = a0.w;
            af[4] = a1.x; af[5] = a1.y; af[6] = a1.z; af[7] = a1.w;
            wf[0] = w0.x; wf[1] = w0.y; wf[2] = w0.z; wf[3] = w0.w;
            wf[4] = w1.x; wf[5] = w1.y; wf[6] = w1.z; wf[7] = w1.w;
#pragma unroll
            for (int i = 0; i < 8; i++)
#pragma unroll
                for (int j = 0; j < 8; j++)
                    acc[i][j] = fmaf(af[i], wf[j], acc[i][j]);
        }
        __syncthreads();
    }

#pragma unroll
    for (int i = 0; i < 8; i++) {
        const size_t r = row0 + ty * 8 + i;
#pragma unroll
        for (int j = 0; j < 8; j++) {
            const int c = col0 + tx * 8 + j;
            C[r * N + c] = activate<ACT>(acc[i][j] + bias[c]);
        }
    }
}

// ---------------- quantum circuit kernel ----------------
// One block (256 threads) per batch row. Amplitude index == tid.
// Qubit q corresponds to bit (7-q) of the flat index (row-major reshape).
// Fuses: row normalization, 6 layers of (8 Rot + 8 CNOT), 24 expectations.
__global__ void __launch_bounds__(256)
quantum_kernel(const float* __restrict__ enc, const float* __restrict__ params,
               float* __restrict__ meas) {
    __shared__ float re[2][256];
    __shared__ float im[2][256];
    __shared__ float sred[3][8];

    const int tid = threadIdx.x;
    const int row = blockIdx.x;
    const int lane = tid & 31;
    const int wid = tid >> 5;

    float v = enc[(size_t)row * 256 + tid];

    // ---- row norm (matches jnp.linalg.norm + max(.,1e-12)) ----
    float ss = v * v;
#pragma unroll
    for (int o = 16; o > 0; o >>= 1) ss += __shfl_xor_sync(0xffffffffu, ss, o);
    if (lane == 0) sred[0][wid] = ss;
    __syncthreads();
    float tot = 0.0f;
#pragma unroll
    for (int w = 0; w < 8; w++) tot += sred[0][w];
    const float nrm = fmaxf(sqrtf(tot), 1e-12f);

    int cur = 0;
    re[0][tid] = v / nrm;
    im[0][tid] = 0.0f;
    __syncthreads();

    for (int l = 0; l < 6; l++) {
        // ---- 8 single-qubit Rot(phi, theta, omega) gates ----
#pragma unroll 1
        for (int q = 0; q < 8; q++) {
            const float phi = params[(l * 8 + q) * 3 + 0];
            const float th  = params[(l * 8 + q) * 3 + 1];
            const float om  = params[(l * 8 + q) * 3 + 2];
            float c, s, ca, sa, cd, sd;
            sincosf(0.5f * th, &s, &c);
            sincosf(0.5f * (phi + om), &sa, &ca);
            sincosf(0.5f * (phi - om), &sd, &cd);

            const int mask = 1 << (7 - q);
            const int pj = tid ^ mask;
            const float ar = re[cur][tid], ai = im[cur][tid];
            const float br = re[cur][pj],  bi = im[cur][pj];
            float nr, ni;
            if ((tid & mask) == 0) {
                // new0 = m00*a + m01*b ; m00=(ca,-sa)*c, m01=(-cd,-sd)*s
                const float m00r = ca * c, m00i = -sa * c;
                const float m01r = -cd * s, m01i = -sd * s;
                nr = m00r * ar - m00i * ai + m01r * br - m01i * bi;
                ni = m00r * ai + m00i * ar + m01r * bi + m01i * br;
            } else {
                // new1 = m10*b + m11*a ; m10=(cd,-sd)*s, m11=(ca,sa)*c
                const float m10r = cd * s, m10i = -sd * s;
                const float m11r = ca * c, m11i = sa * c;
                nr = m10r * br - m10i * bi + m11r * ar - m11i * ai;
                ni = m10r * bi + m10i * br + m11r * ai + m11i * ar;
            }
            re[cur ^ 1][tid] = nr;
            im[cur ^ 1][tid] = ni;
            __syncthreads();
            cur ^= 1;
        }

        // ---- ring of CNOTs, range r = l % 7 + 1 ----
        const int r = l % 7 + 1;
#pragma unroll 1
        for (int q = 0; q < 8; q++) {
            const int cmask = 1 << (7 - q);
            const int tmask = 1 << (7 - ((q + r) & 7));
            const int src = (tid & cmask) ? (tid ^ tmask) : tid;
            const float nr = re[cur][src];
            const float ni = im[cur][src];
            re[cur ^ 1][tid] = nr;
            im[cur ^ 1][tid] = ni;
            __syncthreads();
            cur ^= 1;
        }
    }

    // ---- expectations: Z, X, Y for each qubit ----
#pragma unroll 1
    for (int q = 0; q < 8; q++) {
        const int mask = 1 << (7 - q);
        const float sign = (tid & mask) ? -1.0f : 1.0f;
        const float ar = re[cur][tid], ai = im[cur][tid];
        const float br = re[cur][tid ^ mask], bi = im[cur][tid ^ mask];
        float z = sign * (ar * ar + ai * ai);
        float x = ar * br + ai * bi;
        float y = sign * (ar * bi - ai * br);
#pragma unroll
        for (int o = 16; o > 0; o >>= 1) {
            z += __shfl_xor_sync(0xffffffffu, z, o);
            x += __shfl_xor_sync(0xffffffffu, x, o);
            y += __shfl_xor_sync(0xffffffffu, y, o);
        }
        if (lane == 0) { sred[0][wid] = z; sred[1][wid] = x; sred[2][wid] = y; }
        __syncthreads();
        if (tid == 0) {
            float Z = 0.0f, X = 0.0f, Y = 0.0f;
#pragma unroll
            for (int w = 0; w < 8; w++) { Z += sred[0][w]; X += sred[1][w]; Y += sred[2][w]; }
            meas[(size_t)row * 24 + q]      = Z;
            meas[(size_t)row * 24 + 8 + q]  = X;
            meas[(size_t)row * 24 + 16 + q] = Y;
        }
        __syncthreads();
    }
}

// ---------------- launch ----------------
extern "C" void kernel_launch(void* const* d_in, const int* in_sizes, int n_in,
                              void* d_out, int out_size) {
    const float* x          = (const float*)d_in[0];
    const float* ew1        = (const float*)d_in[1];
    const float* eb1        = (const float*)d_in[2];
    const float* ew2        = (const float*)d_in[3];
    const float* eb2        = (const float*)d_in[4];
    const float* ew3        = (const float*)d_in[5];
    const float* eb3        = (const float*)d_in[6];
    const float* dec_params = (const float*)d_in[7];
    const float* dw1        = (const float*)d_in[8];
    const float* db1        = (const float*)d_in[9];
    const float* dw2        = (const float*)d_in[10];
    const float* db2        = (const float*)d_in[11];
    const float* dw3        = (const float*)d_in[12];
    const float* db3        = (const float*)d_in[13];
    const float* dw4        = (const float*)d_in[14];
    const float* db4        = (const float*)d_in[15];
    const float* dw5        = (const float*)d_in[16];
    const float* db5        = (const float*)d_in[17];
    float* out = (float*)d_out;

    float *h1, *h2, *enc, *meas, *d1, *d2, *d3, *d4;
    cudaGetSymbolAddress((void**)&h1, g_h1);
    cudaGetSymbolAddress((void**)&h2, g_h2);
    cudaGetSymbolAddress((void**)&enc, g_enc);
    cudaGetSymbolAddress((void**)&meas, g_meas);
    cudaGetSymbolAddress((void**)&d1, g_d1);
    cudaGetSymbolAddress((void**)&d2, g_d2);
    cudaGetSymbolAddress((void**)&d3, g_d3);
    cudaGetSymbolAddress((void**)&d4, g_d4);

    const dim3 blk(256);
    const int MB = BATCH / 128;

    // encoder
    sgemm_bias_act<1><<<dim3(1024 / 128, MB), blk>>>(x,  ew1, eb1, h1,  BATCH, 1024, 2560);
    sgemm_bias_act<1><<<dim3(512 / 128,  MB), blk>>>(h1, ew2, eb2, h2,  BATCH, 512,  1024);
    sgemm_bias_act<2><<<dim3(256 / 128,  MB), blk>>>(h2, ew3, eb3, enc, BATCH, 256,  512);

    // quantum circuit (fused normalization + sim + measurements)
    quantum_kernel<<<BATCH, 256>>>(enc, dec_params, meas);

    // decoder
    sgemm_bias_act<1><<<dim3(128 / 128,  MB), blk>>>(meas, dw1, db1, d1, BATCH, 128,  24);
    sgemm_bias_act<1><<<dim3(256 / 128,  MB), blk>>>(d1,   dw2, db2, d2, BATCH, 256,  128);
    sgemm_bias_act<1><<<dim3(512 / 128,  MB), blk>>>(d2,   dw3, db3, d3, BATCH, 512,  256);
    sgemm_bias_act<1><<<dim3(1024 / 128, MB), blk>>>(d3,   dw4, db4, d4, BATCH, 1024, 512);
    sgemm_bias_act<2><<<dim3(2560 / 128, MB), blk>>>(d4,   dw5, db5, out, BATCH, 2560, 1024);
}

// round 3
// speedup vs baseline: 1.9968x; 1.9968x over previous
#include <cuda_runtime.h>
#include <cuda_bf16.h>
#include <math.h>
#include <stdint.h>

#define BATCH 4096
#define MBLOCKS 32

// ---------------------------------------------------------------- PTX helpers
__device__ __forceinline__ uint32_t smem_u32(const void* p) {
    uint32_t a;
    asm("{ .reg .u64 t; cvta.to.shared.u64 t, %1; cvt.u32.u64 %0, t; }" : "=r"(a) : "l"(p));
    return a;
}
__device__ __forceinline__ void cp16(uint32_t s, const void* g) {
    asm volatile("cp.async.cg.shared.global [%0], [%1], 16;" :: "r"(s), "l"(g));
}
__device__ __forceinline__ void cp_commit() { asm volatile("cp.async.commit_group;" ::: "memory"); }
__device__ __forceinline__ void cp_wait1() { asm volatile("cp.async.wait_group 1;" ::: "memory"); }

__device__ __forceinline__ void ldsm_x4(uint32_t* r, uint32_t addr) {
    asm volatile("ldmatrix.sync.aligned.m8n8.x4.shared.b16 {%0,%1,%2,%3}, [%4];"
                 : "=r"(r[0]), "=r"(r[1]), "=r"(r[2]), "=r"(r[3]) : "r"(addr));
}
__device__ __forceinline__ void ldsm_x4t(uint32_t* r, uint32_t addr) {
    asm volatile("ldmatrix.sync.aligned.m8n8.x4.trans.shared.b16 {%0,%1,%2,%3}, [%4];"
                 : "=r"(r[0]), "=r"(r[1]), "=r"(r[2]), "=r"(r[3]) : "r"(addr));
}
__device__ __forceinline__ void mma_bf16(float* c, const uint32_t* a, const uint32_t* b) {
    asm volatile(
        "mma.sync.aligned.m16n8k16.row.col.f32.bf16.bf16.f32 "
        "{%0,%1,%2,%3}, {%4,%5,%6,%7}, {%8,%9}, {%0,%1,%2,%3};"
        : "+f"(c[0]), "+f"(c[1]), "+f"(c[2]), "+f"(c[3])
        : "r"(a[0]), "r"(a[1]), "r"(a[2]), "r"(a[3]), "r"(b[0]), "r"(b[1]));
}

// ---------------------------------------------------------------- scratch
// activation hi/lo planes (row-major bf16), elem offsets:
#define X_OFF   0u
#define H1_OFF  10485760u
#define H2_OFF  14680064u
#define MS_OFF  16777216u
#define D1_OFF  16908288u
#define D2_OFF  17432576u
#define D3_OFF  18481152u
#define D4_OFF  20578304u
#define ACT_TOTAL 24772608u
// weight hi/lo planes (row-major (Kp,N) bf16):
#define W1_OFF  0u
#define W2_OFF  2621440u
#define W3_OFF  3145728u
#define W4_OFF  3276800u
#define W5_OFF  3280896u
#define W6_OFF  3313664u
#define W7_OFF  3444736u
#define W8_OFF  3969024u
#define WT_TOTAL 6590464u

__device__ __align__(16) __nv_bfloat16 g_act_h[ACT_TOTAL];
__device__ __align__(16) __nv_bfloat16 g_act_l[ACT_TOTAL];
__device__ __align__(16) __nv_bfloat16 g_wt_h[WT_TOTAL];
__device__ __align__(16) __nv_bfloat16 g_wt_l[WT_TOTAL];
__device__ float g_enc[BATCH * 256];

// ---------------------------------------------------------------- conversions
__global__ void conv_split(const float* __restrict__ in, __nv_bfloat16* __restrict__ hi,
                           __nv_bfloat16* __restrict__ lo) {
    uint32_t i = blockIdx.x * 256u + threadIdx.x;
    float v = in[i];
    __nv_bfloat16 h = __float2bfloat16(v);
    hi[i] = h;
    lo[i] = __float2bfloat16(v - __bfloat162float(h));
}

// pads k >= Kreal with zeros; grid covers Kpad*N threads
__global__ void conv_wpad(const float* __restrict__ W, __nv_bfloat16* __restrict__ hi,
                          __nv_bfloat16* __restrict__ lo, int N, int Kreal) {
    uint32_t i = blockIdx.x * 256u + threadIdx.x;
    uint32_t k = i / (uint32_t)N, n = i % (uint32_t)N;
    float v = (k < (uint32_t)Kreal) ? W[(size_t)k * N + n] : 0.0f;
    __nv_bfloat16 h = __float2bfloat16(v);
    hi[i] = h;
    lo[i] = __float2bfloat16(v - __bfloat162float(h));
}

// ---------------------------------------------------------------- mma.sync GEMM
// C = act(A @ B + bias). A: (4096, Kp) hi/lo bf16 row-major, B: (Kp, N) hi/lo
// bf16 row-major. Kp % 32 == 0, N % 128 == 0. acc = Ah*Bh + Ah*Bl + Al*Bh (fp32).
// Output: fp32 row-major (outf) or hi/lo bf16 planes (Oh/Ol).
// grid = (N/128, 32), block = 256 (8 warps: 2 in M x 4 in N; warp tile 64x32).
#define A_PLANE 10240u   // 128 rows * 80 B
#define B_PLANE 8704u    // 32 rows * 272 B
#define STAGE_BYTES 37888u
#define GEMM_SMEM (3u * STAGE_BYTES)

__global__ void __launch_bounds__(256, 1)
gemm_mma(const __nv_bfloat16* __restrict__ Ah, const __nv_bfloat16* __restrict__ Al,
         const __nv_bfloat16* __restrict__ Bh, const __nv_bfloat16* __restrict__ Bl,
         const float* __restrict__ bias, float* __restrict__ outf,
         __nv_bfloat16* __restrict__ Oh, __nv_bfloat16* __restrict__ Ol,
         int N, int Kp, int act) {
    extern __shared__ char smem[];
    const uint32_t sb = smem_u32(smem);
    const int tid = threadIdx.x;
    const int lane = tid & 31, warp = tid >> 5;
    const int wm = warp & 1, wn = warp >> 1;
    const int mblock = blockIdx.y, nblock = blockIdx.x;
    const int Kc = Kp >> 5;

#define ISSUE(c, s) do {                                                            \
        const uint32_t st_ = sb + (uint32_t)(s) * STAGE_BYTES;                      \
        const int k0_ = (c) << 5;                                                   \
        for (int j = 0; j < 2; j++) {                                               \
            int i = tid + j * 256;                                                  \
            int row = i >> 2, kc = i & 3;                                           \
            size_t go = (size_t)(mblock * 128 + row) * Kp + k0_ + kc * 8;           \
            uint32_t so = st_ + row * 80 + kc * 16;                                 \
            cp16(so, Ah + go);                                                      \
            cp16(so + A_PLANE, Al + go);                                            \
        }                                                                           \
        for (int j = 0; j < 2; j++) {                                               \
            int i = tid + j * 256;                                                  \
            int row = i >> 4, nc = i & 15;                                          \
            size_t go = (size_t)(k0_ + row) * N + nblock * 128 + nc * 8;            \
            uint32_t so = st_ + 2 * A_PLANE + row * 272 + nc * 16;                  \
            cp16(so, Bh + go);                                                      \
            cp16(so + B_PLANE, Bl + go);                                            \
        }                                                                           \
    } while (0)

    ISSUE(0, 0);
    cp_commit();
    if (Kc > 1) ISSUE(1, 1);
    cp_commit();

    float acc[4][4][4];
#pragma unroll
    for (int mt = 0; mt < 4; mt++)
#pragma unroll
        for (int nt = 0; nt < 4; nt++)
#pragma unroll
            for (int t = 0; t < 4; t++) acc[mt][nt][t] = 0.0f;

    for (int c = 0; c < Kc; c++) {
        cp_wait1();
        __syncthreads();
        if (c + 2 < Kc) ISSUE(c + 2, (c + 2) % 3);
        cp_commit();

        const uint32_t st = sb + (uint32_t)(c % 3) * STAGE_BYTES;
#pragma unroll
        for (int kk = 0; kk < 32; kk += 16) {
            uint32_t ahf[4][4], alf[4][4];
#pragma unroll
            for (int mt = 0; mt < 4; mt++) {
                int row = wm * 64 + mt * 16 + (lane & 15);
                int kc = (kk >> 3) + (lane >> 4);
                uint32_t ad = st + row * 80 + kc * 16;
                ldsm_x4(ahf[mt], ad);
                ldsm_x4(alf[mt], ad + A_PLANE);
            }
            uint32_t bhf[4][2], blf[4][2];
#pragma unroll
            for (int np = 0; np < 2; np++) {
                int row = kk + (lane & 15);
                int nc = ((wn * 32 + np * 16) >> 3) + (lane >> 4);
                uint32_t bd = st + 2 * A_PLANE + row * 272 + nc * 16;
                uint32_t r[4];
                ldsm_x4t(r, bd);
                bhf[np * 2][0] = r[0]; bhf[np * 2][1] = r[1];
                bhf[np * 2 + 1][0] = r[2]; bhf[np * 2 + 1][1] = r[3];
                ldsm_x4t(r, bd + B_PLANE);
                blf[np * 2][0] = r[0]; blf[np * 2][1] = r[1];
                blf[np * 2 + 1][0] = r[2]; blf[np * 2 + 1][1] = r[3];
            }
#pragma unroll
            for (int mt = 0; mt < 4; mt++)
#pragma unroll
                for (int nt = 0; nt < 4; nt++) {
                    mma_bf16(acc[mt][nt], ahf[mt], bhf[nt]);
                    mma_bf16(acc[mt][nt], ahf[mt], blf[nt]);
                    mma_bf16(acc[mt][nt], alf[mt], bhf[nt]);
                }
        }
    }

    // ---------------- epilogue ----------------
#pragma unroll
    for (int mt = 0; mt < 4; mt++) {
#pragma unroll
        for (int nt = 0; nt < 4; nt++) {
            const int r0 = mblock * 128 + wm * 64 + mt * 16 + (lane >> 2);
            const int cc = nblock * 128 + wn * 32 + nt * 8 + (lane & 3) * 2;
            const float2 bv = *reinterpret_cast<const float2*>(&bias[cc]);
            float v[4];
            v[0] = acc[mt][nt][0] + bv.x;
            v[1] = acc[mt][nt][1] + bv.y;
            v[2] = acc[mt][nt][2] + bv.x;
            v[3] = acc[mt][nt][3] + bv.y;
#pragma unroll
            for (int t = 0; t < 4; t++)
                v[t] = (act == 1) ? (v[t] >= 0.0f ? v[t] : 0.2f * v[t]) : tanhf(v[t]);
            if (outf) {
                *reinterpret_cast<float2*>(&outf[(size_t)r0 * N + cc]) = make_float2(v[0], v[1]);
                *reinterpret_cast<float2*>(&outf[(size_t)(r0 + 8) * N + cc]) = make_float2(v[2], v[3]);
            } else {
#pragma unroll
                for (int rr = 0; rr < 2; rr++) {
                    const float a0 = v[rr * 2 + 0], a1 = v[rr * 2 + 1];
                    __nv_bfloat16 h0 = __float2bfloat16(a0);
                    __nv_bfloat16 h1 = __float2bfloat16(a1);
                    __nv_bfloat162 hp, lp;
                    hp.x = h0; hp.y = h1;
                    lp.x = __float2bfloat16(a0 - __bfloat162float(h0));
                    lp.y = __float2bfloat16(a1 - __bfloat162float(h1));
                    const size_t o = (size_t)(r0 + rr * 8) * N + cc;
                    *reinterpret_cast<__nv_bfloat162*>(&Oh[o]) = hp;
                    *reinterpret_cast<__nv_bfloat162*>(&Ol[o]) = lp;
                }
            }
        }
    }
#undef ISSUE
}

// ---------------------------------------------------------------- quantum circuit
// One block (256 threads) per batch row. Reads fp32 enc, writes meas hi/lo
// planes (4096 x 32 row-major, cols 24..31 zero).
__global__ void __launch_bounds__(256)
quantum_kernel(const float* __restrict__ enc, const float* __restrict__ params,
               __nv_bfloat16* __restrict__ mh, __nv_bfloat16* __restrict__ ml) {
    __shared__ float re[2][256];
    __shared__ float im[2][256];
    __shared__ float sred[3][8];
    __shared__ float sm_meas[24];

    const int tid = threadIdx.x;
    const int row = blockIdx.x;
    const int lane = tid & 31;
    const int wid = tid >> 5;

    float v = enc[(size_t)row * 256 + tid];

    float ss = v * v;
#pragma unroll
    for (int o = 16; o > 0; o >>= 1) ss += __shfl_xor_sync(0xffffffffu, ss, o);
    if (lane == 0) sred[0][wid] = ss;
    __syncthreads();
    float tot = 0.0f;
#pragma unroll
    for (int w = 0; w < 8; w++) tot += sred[0][w];
    const float nrm = fmaxf(sqrtf(tot), 1e-12f);

    int cur = 0;
    re[0][tid] = v / nrm;
    im[0][tid] = 0.0f;
    __syncthreads();

    for (int l = 0; l < 6; l++) {
#pragma unroll 1
        for (int q = 0; q < 8; q++) {
            const float phi = params[(l * 8 + q) * 3 + 0];
            const float th  = params[(l * 8 + q) * 3 + 1];
            const float om  = params[(l * 8 + q) * 3 + 2];
            float c, s, ca, sa, cd, sd;
            sincosf(0.5f * th, &s, &c);
            sincosf(0.5f * (phi + om), &sa, &ca);
            sincosf(0.5f * (phi - om), &sd, &cd);

            const int mask = 1 << (7 - q);
            const int pj = tid ^ mask;
            const float ar = re[cur][tid], ai = im[cur][tid];
            const float br = re[cur][pj],  bi = im[cur][pj];
            float nr, ni;
            if ((tid & mask) == 0) {
                const float m00r = ca * c, m00i = -sa * c;
                const float m01r = -cd * s, m01i = -sd * s;
                nr = m00r * ar - m00i * ai + m01r * br - m01i * bi;
                ni = m00r * ai + m00i * ar + m01r * bi + m01i * br;
            } else {
                const float m10r = cd * s, m10i = -sd * s;
                const float m11r = ca * c, m11i = sa * c;
                nr = m10r * br - m10i * bi + m11r * ar - m11i * ai;
                ni = m10r * bi + m10i * br + m11r * ai + m11i * ar;
            }
            re[cur ^ 1][tid] = nr;
            im[cur ^ 1][tid] = ni;
            __syncthreads();
            cur ^= 1;
        }

        const int r = l % 7 + 1;
#pragma unroll 1
        for (int q = 0; q < 8; q++) {
            const int cmask = 1 << (7 - q);
            const int tmask = 1 << (7 - ((q + r) & 7));
            const int src = (tid & cmask) ? (tid ^ tmask) : tid;
            const float nr = re[cur][src];
            const float ni = im[cur][src];
            re[cur ^ 1][tid] = nr;
            im[cur ^ 1][tid] = ni;
            __syncthreads();
            cur ^= 1;
        }
    }

#pragma unroll 1
    for (int q = 0; q < 8; q++) {
        const int mask = 1 << (7 - q);
        const float sign = (tid & mask) ? -1.0f : 1.0f;
        const float ar = re[cur][tid], ai = im[cur][tid];
        const float br = re[cur][tid ^ mask], bi = im[cur][tid ^ mask];
        float z = sign * (ar * ar + ai * ai);
        float x = ar * br + ai * bi;
        float y = sign * (ar * bi - ai * br);
#pragma unroll
        for (int o = 16; o > 0; o >>= 1) {
            z += __shfl_xor_sync(0xffffffffu, z, o);
            x += __shfl_xor_sync(0xffffffffu, x, o);
            y += __shfl_xor_sync(0xffffffffu, y, o);
        }
        if (lane == 0) { sred[0][wid] = z; sred[1][wid] = x; sred[2][wid] = y; }
        __syncthreads();
        if (tid == 0) {
            float Z = 0.0f, X = 0.0f, Y = 0.0f;
#pragma unroll
            for (int w = 0; w < 8; w++) { Z += sred[0][w]; X += sred[1][w]; Y += sred[2][w]; }
            sm_meas[q] = Z; sm_meas[8 + q] = X; sm_meas[16 + q] = Y;
        }
        __syncthreads();
    }

    if (tid < 32) {
        float mv = (tid < 24) ? sm_meas[tid] : 0.0f;
        __nv_bfloat16 h = __float2bfloat16(mv);
        mh[(size_t)row * 32 + tid] = h;
        ml[(size_t)row * 32 + tid] = __float2bfloat16(mv - __bfloat162float(h));
    }
}

// ---------------------------------------------------------------- launch
extern "C" void kernel_launch(void* const* d_in, const int* in_sizes, int n_in,
                              void* d_out, int out_size) {
    const float* x          = (const float*)d_in[0];
    const float* ew1        = (const float*)d_in[1];
    const float* eb1        = (const float*)d_in[2];
    const float* ew2        = (const float*)d_in[3];
    const float* eb2        = (const float*)d_in[4];
    const float* ew3        = (const float*)d_in[5];
    const float* eb3        = (const float*)d_in[6];
    const float* dec_params = (const float*)d_in[7];
    const float* dw1        = (const float*)d_in[8];
    const float* db1        = (const float*)d_in[9];
    const float* dw2        = (const float*)d_in[10];
    const float* db2        = (const float*)d_in[11];
    const float* dw3        = (const float*)d_in[12];
    const float* db3        = (const float*)d_in[13];
    const float* dw4        = (const float*)d_in[14];
    const float* db4        = (const float*)d_in[15];
    const float* dw5        = (const float*)d_in[16];
    const float* db5        = (const float*)d_in[17];
    float* out = (float*)d_out;

    __nv_bfloat16 *ah, *al, *wh, *wl;
    float* enc;
    cudaGetSymbolAddress((void**)&ah, g_act_h);
    cudaGetSymbolAddress((void**)&al, g_act_l);
    cudaGetSymbolAddress((void**)&wh, g_wt_h);
    cudaGetSymbolAddress((void**)&wl, g_wt_l);
    cudaGetSymbolAddress((void**)&enc, g_enc);

    cudaFuncSetAttribute(gemm_mma, cudaFuncAttributeMaxDynamicSharedMemorySize, GEMM_SMEM);

    // ---- conversions ----
    conv_split<<<(BATCH * 2560) / 256, 256>>>(x, ah + X_OFF, al + X_OFF);
    conv_split<<<(2560 * 1024) / 256, 256>>>(ew1, wh + W1_OFF, wl + W1_OFF);
    conv_split<<<(1024 * 512) / 256, 256>>>(ew2, wh + W2_OFF, wl + W2_OFF);
    conv_split<<<(512 * 256) / 256, 256>>>(ew3, wh + W3_OFF, wl + W3_OFF);
    conv_wpad<<<(32 * 128) / 256, 256>>>(dw1, wh + W4_OFF, wl + W4_OFF, 128, 24);
    conv_split<<<(128 * 256) / 256, 256>>>(dw2, wh + W5_OFF, wl + W5_OFF);
    conv_split<<<(256 * 512) / 256, 256>>>(dw3, wh + W6_OFF, wl + W6_OFF);
    conv_split<<<(512 * 1024) / 256, 256>>>(dw4, wh + W7_OFF, wl + W7_OFF);
    conv_split<<<(1024 * 2560) / 256, 256>>>(dw5, wh + W8_OFF, wl + W8_OFF);

    // ---- encoder ----
    gemm_mma<<<dim3(8, MBLOCKS), 256, GEMM_SMEM>>>(ah + X_OFF, al + X_OFF, wh + W1_OFF, wl + W1_OFF,
                                                   eb1, nullptr, ah + H1_OFF, al + H1_OFF, 1024, 2560, 1);
    gemm_mma<<<dim3(4, MBLOCKS), 256, GEMM_SMEM>>>(ah + H1_OFF, al + H1_OFF, wh + W2_OFF, wl + W2_OFF,
                                                   eb2, nullptr, ah + H2_OFF, al + H2_OFF, 512, 1024, 1);
    gemm_mma<<<dim3(2, MBLOCKS), 256, GEMM_SMEM>>>(ah + H2_OFF, al + H2_OFF, wh + W3_OFF, wl + W3_OFF,
                                                   eb3, enc, nullptr, nullptr, 256, 512, 2);

    // ---- quantum ----
    quantum_kernel<<<BATCH, 256>>>(enc, dec_params, ah + MS_OFF, al + MS_OFF);

    // ---- decoder ----
    gemm_mma<<<dim3(1, MBLOCKS), 256, GEMM_SMEM>>>(ah + MS_OFF, al + MS_OFF, wh + W4_OFF, wl + W4_OFF,
                                                   db1, nullptr, ah + D1_OFF, al + D1_OFF, 128, 32, 1);
    gemm_mma<<<dim3(2, MBLOCKS), 256, GEMM_SMEM>>>(ah + D1_OFF, al + D1_OFF, wh + W5_OFF, wl + W5_OFF,
                                                   db2, nullptr, ah + D2_OFF, al + D2_OFF, 256, 128, 1);
    gemm_mma<<<dim3(4, MBLOCKS), 256, GEMM_SMEM>>>(ah + D2_OFF, al + D2_OFF, wh + W6_OFF, wl + W6_OFF,
                                                   db3, nullptr, ah + D3_OFF, al + D3_OFF, 512, 256, 1);
    gemm_mma<<<dim3(8, MBLOCKS), 256, GEMM_SMEM>>>(ah + D3_OFF, al + D3_OFF, wh + W7_OFF, wl + W7_OFF,
                                                   db4, nullptr, ah + D4_OFF, al + D4_OFF, 1024, 512, 1);
    gemm_mma<<<dim3(20, MBLOCKS), 256, GEMM_SMEM>>>(ah + D4_OFF, al + D4_OFF, wh + W8_OFF, wl + W8_OFF,
                                                    db5, out, nullptr, nullptr, 2560, 1024, 2);
}

// round 4
// speedup vs baseline: 2.4403x; 1.2221x over previous
#include <cuda_runtime.h>
#include <cuda_bf16.h>
#include <math.h>
#include <stdint.h>

#define BATCH 4096
#define MBLOCKS 32

// ---------------------------------------------------------------- PTX helpers
__device__ __forceinline__ uint32_t smem_u32(const void* p) {
    uint32_t a;
    asm("{ .reg .u64 t; cvta.to.shared.u64 t, %1; cvt.u32.u64 %0, t; }" : "=r"(a) : "l"(p));
    return a;
}
__device__ __forceinline__ void cp16(uint32_t s, const void* g) {
    asm volatile("cp.async.cg.shared.global [%0], [%1], 16;" :: "r"(s), "l"(g));
}
__device__ __forceinline__ void cp_commit() { asm volatile("cp.async.commit_group;" ::: "memory"); }
__device__ __forceinline__ void cp_wait1() { asm volatile("cp.async.wait_group 1;" ::: "memory"); }

__device__ __forceinline__ void ldsm_x4(uint32_t* r, uint32_t addr) {
    asm volatile("ldmatrix.sync.aligned.m8n8.x4.shared.b16 {%0,%1,%2,%3}, [%4];"
                 : "=r"(r[0]), "=r"(r[1]), "=r"(r[2]), "=r"(r[3]) : "r"(addr));
}
__device__ __forceinline__ void ldsm_x4t(uint32_t* r, uint32_t addr) {
    asm volatile("ldmatrix.sync.aligned.m8n8.x4.trans.shared.b16 {%0,%1,%2,%3}, [%4];"
                 : "=r"(r[0]), "=r"(r[1]), "=r"(r[2]), "=r"(r[3]) : "r"(addr));
}
__device__ __forceinline__ void mma_bf16(float* c, const uint32_t* a, const uint32_t* b) {
    asm volatile(
        "mma.sync.aligned.m16n8k16.row.col.f32.bf16.bf16.f32 "
        "{%0,%1,%2,%3}, {%4,%5,%6,%7}, {%8,%9}, {%0,%1,%2,%3};"
        : "+f"(c[0]), "+f"(c[1]), "+f"(c[2]), "+f"(c[3])
        : "r"(a[0]), "r"(a[1]), "r"(a[2]), "r"(a[3]), "r"(b[0]), "r"(b[1]));
}

// ---------------------------------------------------------------- scratch
#define X_OFF   0u
#define H1_OFF  10485760u
#define H2_OFF  14680064u
#define MS_OFF  16777216u
#define D1_OFF  16908288u
#define D2_OFF  17432576u
#define D3_OFF  18481152u
#define D4_OFF  20578304u
#define ACT_TOTAL 24772608u
#define W1_OFF  0u
#define W2_OFF  2621440u
#define W3_OFF  3145728u
#define W4_OFF  3276800u
#define W5_OFF  3280896u
#define W6_OFF  3313664u
#define W7_OFF  3444736u
#define W8_OFF  3969024u
#define WT_TOTAL 6590464u

__device__ __align__(16) __nv_bfloat16 g_act_h[ACT_TOTAL];
__device__ __align__(16) __nv_bfloat16 g_act_l[ACT_TOTAL];
__device__ __align__(16) __nv_bfloat16 g_wt_h[WT_TOTAL];
__device__ __align__(16) __nv_bfloat16 g_wt_l[WT_TOTAL];
__device__ float g_enc[BATCH * 256];

// ---------------------------------------------------------------- conversions
__global__ void conv_split(const float* __restrict__ in, __nv_bfloat16* __restrict__ hi,
                           __nv_bfloat16* __restrict__ lo) {
    uint32_t i = blockIdx.x * 256u + threadIdx.x;
    float v = in[i];
    __nv_bfloat16 h = __float2bfloat16(v);
    hi[i] = h;
    lo[i] = __float2bfloat16(v - __bfloat162float(h));
}

__global__ void conv_wpad(const float* __restrict__ W, __nv_bfloat16* __restrict__ hi,
                          __nv_bfloat16* __restrict__ lo, int N, int Kreal) {
    uint32_t i = blockIdx.x * 256u + threadIdx.x;
    uint32_t k = i / (uint32_t)N, n = i % (uint32_t)N;
    float v = (k < (uint32_t)Kreal) ? W[(size_t)k * N + n] : 0.0f;
    __nv_bfloat16 h = __float2bfloat16(v);
    hi[i] = h;
    lo[i] = __float2bfloat16(v - __bfloat162float(h));
}

// ---------------------------------------------------------------- mma.sync GEMM
#define A_PLANE 10240u
#define B_PLANE 8704u
#define STAGE_BYTES 37888u
#define GEMM_SMEM (3u * STAGE_BYTES)

__global__ void __launch_bounds__(256, 1)
gemm_mma(const __nv_bfloat16* __restrict__ Ah, const __nv_bfloat16* __restrict__ Al,
         const __nv_bfloat16* __restrict__ Bh, const __nv_bfloat16* __restrict__ Bl,
         const float* __restrict__ bias, float* __restrict__ outf,
         __nv_bfloat16* __restrict__ Oh, __nv_bfloat16* __restrict__ Ol,
         int N, int Kp, int act) {
    extern __shared__ char smem[];
    const uint32_t sb = smem_u32(smem);
    const int tid = threadIdx.x;
    const int lane = tid & 31, warp = tid >> 5;
    const int wm = warp & 1, wn = warp >> 1;
    const int mblock = blockIdx.y, nblock = blockIdx.x;
    const int Kc = Kp >> 5;

#define ISSUE(c, s) do {                                                            \
        const uint32_t st_ = sb + (uint32_t)(s) * STAGE_BYTES;                      \
        const int k0_ = (c) << 5;                                                   \
        for (int j = 0; j < 2; j++) {                                               \
            int i = tid + j * 256;                                                  \
            int row = i >> 2, kc = i & 3;                                           \
            size_t go = (size_t)(mblock * 128 + row) * Kp + k0_ + kc * 8;           \
            uint32_t so = st_ + row * 80 + kc * 16;                                 \
            cp16(so, Ah + go);                                                      \
            cp16(so + A_PLANE, Al + go);                                            \
        }                                                                           \
        for (int j = 0; j < 2; j++) {                                               \
            int i = tid + j * 256;                                                  \
            int row = i >> 4, nc = i & 15;                                          \
            size_t go = (size_t)(k0_ + row) * N + nblock * 128 + nc * 8;            \
            uint32_t so = st_ + 2 * A_PLANE + row * 272 + nc * 16;                  \
            cp16(so, Bh + go);                                                      \
            cp16(so + B_PLANE, Bl + go);                                            \
        }                                                                           \
    } while (0)

    ISSUE(0, 0);
    cp_commit();
    if (Kc > 1) ISSUE(1, 1);
    cp_commit();

    float acc[4][4][4];
#pragma unroll
    for (int mt = 0; mt < 4; mt++)
#pragma unroll
        for (int nt = 0; nt < 4; nt++)
#pragma unroll
            for (int t = 0; t < 4; t++) acc[mt][nt][t] = 0.0f;

    for (int c = 0; c < Kc; c++) {
        cp_wait1();
        __syncthreads();
        if (c + 2 < Kc) ISSUE(c + 2, (c + 2) % 3);
        cp_commit();

        const uint32_t st = sb + (uint32_t)(c % 3) * STAGE_BYTES;
#pragma unroll
        for (int kk = 0; kk < 32; kk += 16) {
            uint32_t ahf[4][4], alf[4][4];
#pragma unroll
            for (int mt = 0; mt < 4; mt++) {
                int row = wm * 64 + mt * 16 + (lane & 15);
                int kc = (kk >> 3) + (lane >> 4);
                uint32_t ad = st + row * 80 + kc * 16;
                ldsm_x4(ahf[mt], ad);
                ldsm_x4(alf[mt], ad + A_PLANE);
            }
            uint32_t bhf[4][2], blf[4][2];
#pragma unroll
            for (int np = 0; np < 2; np++) {
                int row = kk + (lane & 15);
                int nc = ((wn * 32 + np * 16) >> 3) + (lane >> 4);
                uint32_t bd = st + 2 * A_PLANE + row * 272 + nc * 16;
                uint32_t r[4];
                ldsm_x4t(r, bd);
                bhf[np * 2][0] = r[0]; bhf[np * 2][1] = r[1];
                bhf[np * 2 + 1][0] = r[2]; bhf[np * 2 + 1][1] = r[3];
                ldsm_x4t(r, bd + B_PLANE);
                blf[np * 2][0] = r[0]; blf[np * 2][1] = r[1];
                blf[np * 2 + 1][0] = r[2]; blf[np * 2 + 1][1] = r[3];
            }
#pragma unroll
            for (int mt = 0; mt < 4; mt++)
#pragma unroll
                for (int nt = 0; nt < 4; nt++) {
                    mma_bf16(acc[mt][nt], ahf[mt], bhf[nt]);
                    mma_bf16(acc[mt][nt], ahf[mt], blf[nt]);
                    mma_bf16(acc[mt][nt], alf[mt], bhf[nt]);
                }
        }
    }

#pragma unroll
    for (int mt = 0; mt < 4; mt++) {
#pragma unroll
        for (int nt = 0; nt < 4; nt++) {
            const int r0 = mblock * 128 + wm * 64 + mt * 16 + (lane >> 2);
            const int cc = nblock * 128 + wn * 32 + nt * 8 + (lane & 3) * 2;
            const float2 bv = *reinterpret_cast<const float2*>(&bias[cc]);
            float v[4];
            v[0] = acc[mt][nt][0] + bv.x;
            v[1] = acc[mt][nt][1] + bv.y;
            v[2] = acc[mt][nt][2] + bv.x;
            v[3] = acc[mt][nt][3] + bv.y;
#pragma unroll
            for (int t = 0; t < 4; t++)
                v[t] = (act == 1) ? (v[t] >= 0.0f ? v[t] : 0.2f * v[t]) : tanhf(v[t]);
            if (outf) {
                *reinterpret_cast<float2*>(&outf[(size_t)r0 * N + cc]) = make_float2(v[0], v[1]);
                *reinterpret_cast<float2*>(&outf[(size_t)(r0 + 8) * N + cc]) = make_float2(v[2], v[3]);
            } else {
#pragma unroll
                for (int rr = 0; rr < 2; rr++) {
                    const float a0 = v[rr * 2 + 0], a1 = v[rr * 2 + 1];
                    __nv_bfloat16 h0 = __float2bfloat16(a0);
                    __nv_bfloat16 h1 = __float2bfloat16(a1);
                    __nv_bfloat162 hp, lp;
                    hp.x = h0; hp.y = h1;
                    lp.x = __float2bfloat16(a0 - __bfloat162float(h0));
                    lp.y = __float2bfloat16(a1 - __bfloat162float(h1));
                    const size_t o = (size_t)(r0 + rr * 8) * N + cc;
                    *reinterpret_cast<__nv_bfloat162*>(&Oh[o]) = hp;
                    *reinterpret_cast<__nv_bfloat162*>(&Ol[o]) = lp;
                }
            }
        }
    }
#undef ISSUE
}

// ---------------------------------------------------------------- quantum circuit
// One WARP per batch row. Lane holds 8 complex amps: idx = r*32 + lane.
// Qubit q: q<3 -> register bit (2-q) of r ; q>=3 -> lane bit (7-q).

template <int Q>
__device__ __forceinline__ void rot_gate(float (&re)[8], float (&im)[8],
                                         float m00r, float m00i, float m01r, float m01i,
                                         float m10r, float m10i, float m11r, float m11i,
                                         int lane) {
    if constexpr (Q < 3) {
        constexpr int rm = 1 << (2 - Q);
#pragma unroll
        for (int r = 0; r < 8; r++)
            if (!(r & rm)) {
                const int p = r | rm;
                const float ar = re[r], ai = im[r], br = re[p], bi = im[p];
                re[r] = m00r * ar - m00i * ai + m01r * br - m01i * bi;
                im[r] = m00r * ai + m00i * ar + m01r * bi + m01i * br;
                re[p] = m10r * ar - m10i * ai + m11r * br - m11i * bi;
                im[p] = m10r * ai + m10i * ar + m11r * bi + m11i * br;
            }
    } else {
        constexpr int lm = 1 << (7 - Q);
        const bool hi = lane & lm;
#pragma unroll
        for (int r = 0; r < 8; r++) {
            const float pr = __shfl_xor_sync(0xffffffffu, re[r], lm);
            const float pi = __shfl_xor_sync(0xffffffffu, im[r], lm);
            const float ar = re[r], ai = im[r];
            if (!hi) {
                re[r] = m00r * ar - m00i * ai + m01r * pr - m01i * pi;
                im[r] = m00r * ai + m00i * ar + m01r * pi + m01i * pr;
            } else {
                re[r] = m10r * pr - m10i * pi + m11r * ar - m11i * ai;
                im[r] = m10r * pi + m10i * pr + m11r * ai + m11i * ar;
            }
        }
    }
}

// CNOT: new[i] = old[i ^ (bit_c(i) ? tmask : 0)]
template <int C, int T>
__device__ __forceinline__ void cnot_gate(float (&re)[8], float (&im)[8], int lane) {
    if constexpr (C < 3 && T < 3) {
        constexpr int cm = 1 << (2 - C), tm = 1 << (2 - T);
#pragma unroll
        for (int r = 0; r < 8; r++)
            if ((r & cm) && !(r & tm)) {
                const int p = r | tm;
                float t;
                t = re[r]; re[r] = re[p]; re[p] = t;
                t = im[r]; im[r] = im[p]; im[p] = t;
            }
    } else if constexpr (C < 3 && T >= 3) {
        constexpr int cm = 1 << (2 - C), tm = 1 << (7 - T);
#pragma unroll
        for (int r = 0; r < 8; r++)
            if (r & cm) {
                re[r] = __shfl_xor_sync(0xffffffffu, re[r], tm);
                im[r] = __shfl_xor_sync(0xffffffffu, im[r], tm);
            }
    } else if constexpr (C >= 3 && T < 3) {
        constexpr int cm = 1 << (7 - C), tm = 1 << (2 - T);
        const bool act = lane & cm;
#pragma unroll
        for (int r = 0; r < 8; r++)
            if (!(r & tm)) {
                const int p = r | tm;
                const float r0 = act ? re[p] : re[r];
                const float r1 = act ? re[r] : re[p];
                const float i0 = act ? im[p] : im[r];
                const float i1 = act ? im[r] : im[p];
                re[r] = r0; re[p] = r1; im[r] = i0; im[p] = i1;
            }
    } else {
        constexpr int cm = 1 << (7 - C), tm = 1 << (7 - T);
        const int src = (lane & cm) ? (lane ^ tm) : lane;
#pragma unroll
        for (int r = 0; r < 8; r++) {
            re[r] = __shfl_sync(0xffffffffu, re[r], src);
            im[r] = __shfl_sync(0xffffffffu, im[r], src);
        }
    }
}

template <int L>
__device__ __forceinline__ void do_layer(float (&re)[8], float (&im)[8],
                                         const float* __restrict__ sp, int lane) {
#define ROTG(Q) {                                                                   \
        const float phi = sp[(L * 8 + Q) * 3 + 0];                                  \
        const float th  = sp[(L * 8 + Q) * 3 + 1];                                  \
        const float om  = sp[(L * 8 + Q) * 3 + 2];                                  \
        float s, c, sa, ca, sd, cd;                                                 \
        sincosf(0.5f * th, &s, &c);                                                 \
        sincosf(0.5f * (phi + om), &sa, &ca);                                       \
        sincosf(0.5f * (phi - om), &sd, &cd);                                       \
        rot_gate<Q>(re, im, ca * c, -sa * c, -cd * s, -sd * s,                      \
                    cd * s, -sd * s, ca * c, sa * c, lane); }
    ROTG(0) ROTG(1) ROTG(2) ROTG(3) ROTG(4) ROTG(5) ROTG(6) ROTG(7)
#undef ROTG
    cnot_gate<0, (0 + L + 1) % 8>(re, im, lane);
    cnot_gate<1, (1 + L + 1) % 8>(re, im, lane);
    cnot_gate<2, (2 + L + 1) % 8>(re, im, lane);
    cnot_gate<3, (3 + L + 1) % 8>(re, im, lane);
    cnot_gate<4, (4 + L + 1) % 8>(re, im, lane);
    cnot_gate<5, (5 + L + 1) % 8>(re, im, lane);
    cnot_gate<6, (6 + L + 1) % 8>(re, im, lane);
    cnot_gate<7, (7 + L + 1) % 8>(re, im, lane);
}

template <int Q>
__device__ __forceinline__ void measure(const float (&re)[8], const float (&im)[8], int lane,
                                        float& Z, float& X, float& Y) {
    float z = 0.0f, x = 0.0f, y = 0.0f;
    if constexpr (Q < 3) {
        constexpr int rm = 1 << (2 - Q);
#pragma unroll
        for (int r = 0; r < 8; r++) {
            const float ar = re[r], ai = im[r];
            const int p = r ^ rm;
            const float br = re[p], bi = im[p];
            const float sign = (r & rm) ? -1.0f : 1.0f;
            z += sign * (ar * ar + ai * ai);
            x += ar * br + ai * bi;
            y += sign * (ar * bi - ai * br);
        }
    } else {
        constexpr int lm = 1 << (7 - Q);
        const float sign = (lane & lm) ? -1.0f : 1.0f;
#pragma unroll
        for (int r = 0; r < 8; r++) {
            const float ar = re[r], ai = im[r];
            const float br = __shfl_xor_sync(0xffffffffu, ar, lm);
            const float bi = __shfl_xor_sync(0xffffffffu, ai, lm);
            z += sign * (ar * ar + ai * ai);
            x += ar * br + ai * bi;
            y += sign * (ar * bi - ai * br);
        }
    }
#pragma unroll
    for (int o = 16; o > 0; o >>= 1) {
        z += __shfl_xor_sync(0xffffffffu, z, o);
        x += __shfl_xor_sync(0xffffffffu, x, o);
        y += __shfl_xor_sync(0xffffffffu, y, o);
    }
    Z = z; X = x; Y = y;
}

__global__ void __launch_bounds__(256)
quantum_kernel(const float* __restrict__ enc, const float* __restrict__ params,
               __nv_bfloat16* __restrict__ mh, __nv_bfloat16* __restrict__ ml) {
    __shared__ float sp[144];
    __shared__ float sm[8][32];

    const int tid = threadIdx.x;
    const int lane = tid & 31, w = tid >> 5;
    if (tid < 144) sp[tid] = params[tid];
    __syncthreads();

    const int row = blockIdx.x * 8 + w;

    float re[8], im[8];
    float ss = 0.0f;
#pragma unroll
    for (int r = 0; r < 8; r++) {
        const float v = enc[(size_t)row * 256 + r * 32 + lane];
        re[r] = v; im[r] = 0.0f;
        ss += v * v;
    }
#pragma unroll
    for (int o = 16; o > 0; o >>= 1) ss += __shfl_xor_sync(0xffffffffu, ss, o);
    const float inv = 1.0f / fmaxf(sqrtf(ss), 1e-12f);
#pragma unroll
    for (int r = 0; r < 8; r++) re[r] *= inv;

    do_layer<0>(re, im, sp, lane);
    do_layer<1>(re, im, sp, lane);
    do_layer<2>(re, im, sp, lane);
    do_layer<3>(re, im, sp, lane);
    do_layer<4>(re, im, sp, lane);
    do_layer<5>(re, im, sp, lane);

#define MEAS(Q) {                                                   \
        float Z, X, Y;                                              \
        measure<Q>(re, im, lane, Z, X, Y);                          \
        if (lane == 0) { sm[w][Q] = Z; sm[w][8 + Q] = X; sm[w][16 + Q] = Y; } }
    MEAS(0) MEAS(1) MEAS(2) MEAS(3) MEAS(4) MEAS(5) MEAS(6) MEAS(7)
#undef MEAS
    __syncwarp();

    const float mv = (lane < 24) ? sm[w][lane] : 0.0f;
    const __nv_bfloat16 h = __float2bfloat16(mv);
    mh[(size_t)row * 32 + lane] = h;
    ml[(size_t)row * 32 + lane] = __float2bfloat16(mv - __bfloat162float(h));
}

// ---------------------------------------------------------------- launch
extern "C" void kernel_launch(void* const* d_in, const int* in_sizes, int n_in,
                              void* d_out, int out_size) {
    const float* x          = (const float*)d_in[0];
    const float* ew1        = (const float*)d_in[1];
    const float* eb1        = (const float*)d_in[2];
    const float* ew2        = (const float*)d_in[3];
    const float* eb2        = (const float*)d_in[4];
    const float* ew3        = (const float*)d_in[5];
    const float* eb3        = (const float*)d_in[6];
    const float* dec_params = (const float*)d_in[7];
    const float* dw1        = (const float*)d_in[8];
    const float* db1        = (const float*)d_in[9];
    const float* dw2        = (const float*)d_in[10];
    const float* db2        = (const float*)d_in[11];
    const float* dw3        = (const float*)d_in[12];
    const float* db3        = (const float*)d_in[13];
    const float* dw4        = (const float*)d_in[14];
    const float* db4        = (const float*)d_in[15];
    const float* dw5        = (const float*)d_in[16];
    const float* db5        = (const float*)d_in[17];
    float* out = (float*)d_out;

    __nv_bfloat16 *ah, *al, *wh, *wl;
    float* enc;
    cudaGetSymbolAddress((void**)&ah, g_act_h);
    cudaGetSymbolAddress((void**)&al, g_act_l);
    cudaGetSymbolAddress((void**)&wh, g_wt_h);
    cudaGetSymbolAddress((void**)&wl, g_wt_l);
    cudaGetSymbolAddress((void**)&enc, g_enc);

    cudaFuncSetAttribute(gemm_mma, cudaFuncAttributeMaxDynamicSharedMemorySize, GEMM_SMEM);

    // ---- conversions ----
    conv_split<<<(BATCH * 2560) / 256, 256>>>(x, ah + X_OFF, al + X_OFF);
    conv_split<<<(2560 * 1024) / 256, 256>>>(ew1, wh + W1_OFF, wl + W1_OFF);
    conv_split<<<(1024 * 512) / 256, 256>>>(ew2, wh + W2_OFF, wl + W2_OFF);
    conv_split<<<(512 * 256) / 256, 256>>>(ew3, wh + W3_OFF, wl + W3_OFF);
    conv_wpad<<<(32 * 128) / 256, 256>>>(dw1, wh + W4_OFF, wl + W4_OFF, 128, 24);
    conv_split<<<(128 * 256) / 256, 256>>>(dw2, wh + W5_OFF, wl + W5_OFF);
    conv_split<<<(256 * 512) / 256, 256>>>(dw3, wh + W6_OFF, wl + W6_OFF);
    conv_split<<<(512 * 1024) / 256, 256>>>(dw4, wh + W7_OFF, wl + W7_OFF);
    conv_split<<<(1024 * 2560) / 256, 256>>>(dw5, wh + W8_OFF, wl + W8_OFF);

    // ---- encoder ----
    gemm_mma<<<dim3(8, MBLOCKS), 256, GEMM_SMEM>>>(ah + X_OFF, al + X_OFF, wh + W1_OFF, wl + W1_OFF,
                                                   eb1, nullptr, ah + H1_OFF, al + H1_OFF, 1024, 2560, 1);
    gemm_mma<<<dim3(4, MBLOCKS), 256, GEMM_SMEM>>>(ah + H1_OFF, al + H1_OFF, wh + W2_OFF, wl + W2_OFF,
                                                   eb2, nullptr, ah + H2_OFF, al + H2_OFF, 512, 1024, 1);
    gemm_mma<<<dim3(2, MBLOCKS), 256, GEMM_SMEM>>>(ah + H2_OFF, al + H2_OFF, wh + W3_OFF, wl + W3_OFF,
                                                   eb3, enc, nullptr, nullptr, 256, 512, 2);

    // ---- quantum (one warp per row) ----
    quantum_kernel<<<BATCH / 8, 256>>>(enc, dec_params, ah + MS_OFF, al + MS_OFF);

    // ---- decoder ----
    gemm_mma<<<dim3(1, MBLOCKS), 256, GEMM_SMEM>>>(ah + MS_OFF, al + MS_OFF, wh + W4_OFF, wl + W4_OFF,
                                                   db1, nullptr, ah + D1_OFF, al + D1_OFF, 128, 32, 1);
    gemm_mma<<<dim3(2, MBLOCKS), 256, GEMM_SMEM>>>(ah + D1_OFF, al + D1_OFF, wh + W5_OFF, wl + W5_OFF,
                                                   db2, nullptr, ah + D2_OFF, al + D2_OFF, 256, 128, 1);
    gemm_mma<<<dim3(4, MBLOCKS), 256, GEMM_SMEM>>>(ah + D2_OFF, al + D2_OFF, wh + W6_OFF, wl + W6_OFF,
                                                   db3, nullptr, ah + D3_OFF, al + D3_OFF, 512, 256, 1);
    gemm_mma<<<dim3(8, MBLOCKS), 256, GEMM_SMEM>>>(ah + D3_OFF, al + D3_OFF, wh + W7_OFF, wl + W7_OFF,
                                                   db4, nullptr, ah + D4_OFF, al + D4_OFF, 1024, 512, 1);
    gemm_mma<<<dim3(20, MBLOCKS), 256, GEMM_SMEM>>>(ah + D4_OFF, al + D4_OFF, wh + W8_OFF, wl + W8_OFF,
                                                    db5, out, nullptr, nullptr, 2560, 1024, 2);
}

// round 5
// speedup vs baseline: 2.7428x; 1.1240x over previous
#include <cuda_runtime.h>
#include <cuda_bf16.h>
#include <math.h>
#include <stdint.h>

#define BATCH 4096
#define MBLOCKS 32

// ---------------------------------------------------------------- PTX helpers
__device__ __forceinline__ uint32_t smem_u32(const void* p) {
    uint32_t a;
    asm("{ .reg .u64 t; cvta.to.shared.u64 t, %1; cvt.u32.u64 %0, t; }" : "=r"(a) : "l"(p));
    return a;
}
__device__ __forceinline__ void cp16(uint32_t s, const void* g) {
    asm volatile("cp.async.cg.shared.global [%0], [%1], 16;" :: "r"(s), "l"(g));
}
__device__ __forceinline__ void cp_commit() { asm volatile("cp.async.commit_group;" ::: "memory"); }
__device__ __forceinline__ void cp_wait1() { asm volatile("cp.async.wait_group 1;" ::: "memory"); }

__device__ __forceinline__ void ldsm_x4(uint32_t* r, uint32_t addr) {
    asm volatile("ldmatrix.sync.aligned.m8n8.x4.shared.b16 {%0,%1,%2,%3}, [%4];"
                 : "=r"(r[0]), "=r"(r[1]), "=r"(r[2]), "=r"(r[3]) : "r"(addr));
}
__device__ __forceinline__ void ldsm_x4t(uint32_t* r, uint32_t addr) {
    asm volatile("ldmatrix.sync.aligned.m8n8.x4.trans.shared.b16 {%0,%1,%2,%3}, [%4];"
                 : "=r"(r[0]), "=r"(r[1]), "=r"(r[2]), "=r"(r[3]) : "r"(addr));
}
__device__ __forceinline__ void mma_bf16(float* c, const uint32_t* a, const uint32_t* b) {
    asm volatile(
        "mma.sync.aligned.m16n8k16.row.col.f32.bf16.bf16.f32 "
        "{%0,%1,%2,%3}, {%4,%5,%6,%7}, {%8,%9}, {%0,%1,%2,%3};"
        : "+f"(c[0]), "+f"(c[1]), "+f"(c[2]), "+f"(c[3])
        : "r"(a[0]), "r"(a[1]), "r"(a[2]), "r"(a[3]), "r"(b[0]), "r"(b[1]));
}

// ---------------------------------------------------------------- scratch
#define X_OFF   0u
#define H1_OFF  10485760u
#define H2_OFF  14680064u
#define MS_OFF  16777216u
#define D1_OFF  16908288u
#define D2_OFF  17432576u
#define D3_OFF  18481152u
#define D4_OFF  20578304u
#define ACT_TOTAL 24772608u
#define W1_OFF  0u
#define W2_OFF  2621440u
#define W3_OFF  3145728u
#define W4_OFF  3276800u
#define W5_OFF  3280896u
#define W6_OFF  3313664u
#define W7_OFF  3444736u
#define W8_OFF  3969024u
#define WT_TOTAL 6590464u

__device__ __align__(16) __nv_bfloat16 g_act_h[ACT_TOTAL];
__device__ __align__(16) __nv_bfloat16 g_act_l[ACT_TOTAL];
__device__ __align__(16) __nv_bfloat16 g_wt_h[WT_TOTAL];
__device__ __align__(16) __nv_bfloat16 g_wt_l[WT_TOTAL];
__device__ float g_enc[BATCH * 256];

// ---------------------------------------------------------------- conversions
// x: float4-vectorized split (count % 1024 == 0)
__global__ void conv_x4(const float* __restrict__ in, __nv_bfloat16* __restrict__ hi,
                        __nv_bfloat16* __restrict__ lo) {
    uint32_t i = (blockIdx.x * 256u + threadIdx.x) * 4u;
    float4 v = *reinterpret_cast<const float4*>(in + i);
    __nv_bfloat16 h[4], l[4];
    h[0] = __float2bfloat16(v.x); l[0] = __float2bfloat16(v.x - __bfloat162float(h[0]));
    h[1] = __float2bfloat16(v.y); l[1] = __float2bfloat16(v.y - __bfloat162float(h[1]));
    h[2] = __float2bfloat16(v.z); l[2] = __float2bfloat16(v.z - __bfloat162float(h[2]));
    h[3] = __float2bfloat16(v.w); l[3] = __float2bfloat16(v.w - __bfloat162float(h[3]));
    *reinterpret_cast<uint2*>(hi + i) = *reinterpret_cast<uint2*>(h);
    *reinterpret_cast<uint2*>(lo + i) = *reinterpret_cast<uint2*>(l);
}

// all 8 weights in one launch; dst arena is contiguous (offsets ascend)
struct WSeg { const float* src; uint32_t off; uint32_t N; uint32_t Kreal; };
struct WTable { WSeg s[8]; };

__global__ void conv_w_all(WTable t, __nv_bfloat16* __restrict__ hi,
                           __nv_bfloat16* __restrict__ lo) {
    uint32_t idx = blockIdx.x * 256u + threadIdx.x;
    int s = 0;
#pragma unroll
    for (int j = 1; j < 8; j++)
        if (idx >= t.s[j].off) s = j;
    const WSeg seg = t.s[s];
    uint32_t i = idx - seg.off;
    uint32_t k = i / seg.N, n = i % seg.N;
    float v = (k < seg.Kreal) ? seg.src[(size_t)k * seg.N + n] : 0.0f;
    __nv_bfloat16 h = __float2bfloat16(v);
    hi[idx] = h;
    lo[idx] = __float2bfloat16(v - __bfloat162float(h));
}

// ---------------------------------------------------------------- mma.sync GEMM
#define A_PLANE 10240u
#define B_PLANE 8704u
#define STAGE_BYTES 37888u
#define GEMM_SMEM (3u * STAGE_BYTES)

__global__ void __launch_bounds__(256, 2)
gemm_mma(const __nv_bfloat16* __restrict__ Ah, const __nv_bfloat16* __restrict__ Al,
         const __nv_bfloat16* __restrict__ Bh, const __nv_bfloat16* __restrict__ Bl,
         const float* __restrict__ bias, float* __restrict__ outf,
         __nv_bfloat16* __restrict__ Oh, __nv_bfloat16* __restrict__ Ol,
         int N, int Kp, int act) {
    extern __shared__ char smem[];
    const uint32_t sb = smem_u32(smem);
    const int tid = threadIdx.x;
    const int lane = tid & 31, warp = tid >> 5;
    const int wm = warp & 1, wn = warp >> 1;
    const int mblock = blockIdx.y, nblock = blockIdx.x;
    const int Kc = Kp >> 5;

#define ISSUE(c, s) do {                                                            \
        const uint32_t st_ = sb + (uint32_t)(s) * STAGE_BYTES;                      \
        const int k0_ = (c) << 5;                                                   \
        for (int j = 0; j < 2; j++) {                                               \
            int i = tid + j * 256;                                                  \
            int row = i >> 2, kc = i & 3;                                           \
            size_t go = (size_t)(mblock * 128 + row) * Kp + k0_ + kc * 8;           \
            uint32_t so = st_ + row * 80 + kc * 16;                                 \
            cp16(so, Ah + go);                                                      \
            cp16(so + A_PLANE, Al + go);                                            \
        }                                                                           \
        for (int j = 0; j < 2; j++) {                                               \
            int i = tid + j * 256;                                                  \
            int row = i >> 4, nc = i & 15;                                          \
            size_t go = (size_t)(k0_ + row) * N + nblock * 128 + nc * 8;            \
            uint32_t so = st_ + 2 * A_PLANE + row * 272 + nc * 16;                  \
            cp16(so, Bh + go);                                                      \
            cp16(so + B_PLANE, Bl + go);                                            \
        }                                                                           \
    } while (0)

    ISSUE(0, 0);
    cp_commit();
    if (Kc > 1) ISSUE(1, 1);
    cp_commit();

    float acc[4][4][4];
#pragma unroll
    for (int mt = 0; mt < 4; mt++)
#pragma unroll
        for (int nt = 0; nt < 4; nt++)
#pragma unroll
            for (int t = 0; t < 4; t++) acc[mt][nt][t] = 0.0f;

    for (int c = 0; c < Kc; c++) {
        cp_wait1();
        __syncthreads();
        if (c + 2 < Kc) ISSUE(c + 2, (c + 2) % 3);
        cp_commit();

        const uint32_t st = sb + (uint32_t)(c % 3) * STAGE_BYTES;
#pragma unroll
        for (int kk = 0; kk < 32; kk += 16) {
            // B fragments once per kk-step (16 regs live)
            uint32_t bhf[4][2], blf[4][2];
#pragma unroll
            for (int np = 0; np < 2; np++) {
                int row = kk + (lane & 15);
                int nc = ((wn * 32 + np * 16) >> 3) + (lane >> 4);
                uint32_t bd = st + 2 * A_PLANE + row * 272 + nc * 16;
                uint32_t r[4];
                ldsm_x4t(r, bd);
                bhf[np * 2][0] = r[0]; bhf[np * 2][1] = r[1];
                bhf[np * 2 + 1][0] = r[2]; bhf[np * 2 + 1][1] = r[3];
                ldsm_x4t(r, bd + B_PLANE);
                blf[np * 2][0] = r[0]; blf[np * 2][1] = r[1];
                blf[np * 2 + 1][0] = r[2]; blf[np * 2 + 1][1] = r[3];
            }
            // A fragments per mt (8 regs live at a time)
#pragma unroll
            for (int mt = 0; mt < 4; mt++) {
                int row = wm * 64 + mt * 16 + (lane & 15);
                int kc = (kk >> 3) + (lane >> 4);
                uint32_t ad = st + row * 80 + kc * 16;
                uint32_t ahf[4], alf[4];
                ldsm_x4(ahf, ad);
                ldsm_x4(alf, ad + A_PLANE);
#pragma unroll
                for (int nt = 0; nt < 4; nt++) {
                    mma_bf16(acc[mt][nt], ahf, bhf[nt]);
                    mma_bf16(acc[mt][nt], ahf, blf[nt]);
                    mma_bf16(acc[mt][nt], alf, bhf[nt]);
                }
            }
        }
    }

    // ---------------- epilogue ----------------
#pragma unroll
    for (int mt = 0; mt < 4; mt++) {
#pragma unroll
        for (int nt = 0; nt < 4; nt++) {
            const int r0 = mblock * 128 + wm * 64 + mt * 16 + (lane >> 2);
            const int cc = nblock * 128 + wn * 32 + nt * 8 + (lane & 3) * 2;
            const float2 bv = *reinterpret_cast<const float2*>(&bias[cc]);
            float v[4];
            v[0] = acc[mt][nt][0] + bv.x;
            v[1] = acc[mt][nt][1] + bv.y;
            v[2] = acc[mt][nt][2] + bv.x;
            v[3] = acc[mt][nt][3] + bv.y;
#pragma unroll
            for (int t = 0; t < 4; t++)
                v[t] = (act == 1) ? (v[t] >= 0.0f ? v[t] : 0.2f * v[t]) : tanhf(v[t]);
            if (outf) {
                *reinterpret_cast<float2*>(&outf[(size_t)r0 * N + cc]) = make_float2(v[0], v[1]);
                *reinterpret_cast<float2*>(&outf[(size_t)(r0 + 8) * N + cc]) = make_float2(v[2], v[3]);
            } else {
#pragma unroll
                for (int rr = 0; rr < 2; rr++) {
                    const float a0 = v[rr * 2 + 0], a1 = v[rr * 2 + 1];
                    __nv_bfloat16 h0 = __float2bfloat16(a0);
                    __nv_bfloat16 h1 = __float2bfloat16(a1);
                    __nv_bfloat162 hp, lp;
                    hp.x = h0; hp.y = h1;
                    lp.x = __float2bfloat16(a0 - __bfloat162float(h0));
                    lp.y = __float2bfloat16(a1 - __bfloat162float(h1));
                    const size_t o = (size_t)(r0 + rr * 8) * N + cc;
                    *reinterpret_cast<__nv_bfloat162*>(&Oh[o]) = hp;
                    *reinterpret_cast<__nv_bfloat162*>(&Ol[o]) = lp;
                }
            }
        }
    }
#undef ISSUE
}

// ---------------------------------------------------------------- quantum circuit
// One WARP per batch row. Lane holds 8 complex amps: idx = r*32 + lane.

template <int Q>
__device__ __forceinline__ void rot_gate(float (&re)[8], float (&im)[8],
                                         float m00r, float m00i, float m01r, float m01i,
                                         float m10r, float m10i, float m11r, float m11i,
                                         int lane) {
    if constexpr (Q < 3) {
        constexpr int rm = 1 << (2 - Q);
#pragma unroll
        for (int r = 0; r < 8; r++)
            if (!(r & rm)) {
                const int p = r | rm;
                const float ar = re[r], ai = im[r], br = re[p], bi = im[p];
                re[r] = m00r * ar - m00i * ai + m01r * br - m01i * bi;
                im[r] = m00r * ai + m00i * ar + m01r * bi + m01i * br;
                re[p] = m10r * ar - m10i * ai + m11r * br - m11i * bi;
                im[p] = m10r * ai + m10i * ar + m11r * bi + m11i * br;
            }
    } else {
        constexpr int lm = 1 << (7 - Q);
        const bool hi = lane & lm;
#pragma unroll
        for (int r = 0; r < 8; r++) {
            const float pr = __shfl_xor_sync(0xffffffffu, re[r], lm);
            const float pi = __shfl_xor_sync(0xffffffffu, im[r], lm);
            const float ar = re[r], ai = im[r];
            if (!hi) {
                re[r] = m00r * ar - m00i * ai + m01r * pr - m01i * pi;
                im[r] = m00r * ai + m00i * ar + m01r * pi + m01i * pr;
            } else {
                re[r] = m10r * pr - m10i * pi + m11r * ar - m11i * ai;
                im[r] = m10r * pi + m10i * pr + m11r * ai + m11i * ar;
            }
        }
    }
}

template <int C, int T>
__device__ __forceinline__ void cnot_gate(float (&re)[8], float (&im)[8], int lane) {
    if constexpr (C < 3 && T < 3) {
        constexpr int cm = 1 << (2 - C), tm = 1 << (2 - T);
#pragma unroll
        for (int r = 0; r < 8; r++)
            if ((r & cm) && !(r & tm)) {
                const int p = r | tm;
                float t;
                t = re[r]; re[r] = re[p]; re[p] = t;
                t = im[r]; im[r] = im[p]; im[p] = t;
            }
    } else if constexpr (C < 3 && T >= 3) {
        constexpr int cm = 1 << (2 - C), tm = 1 << (7 - T);
#pragma unroll
        for (int r = 0; r < 8; r++)
            if (r & cm) {
                re[r] = __shfl_xor_sync(0xffffffffu, re[r], tm);
                im[r] = __shfl_xor_sync(0xffffffffu, im[r], tm);
            }
    } else if constexpr (C >= 3 && T < 3) {
        constexpr int cm = 1 << (7 - C), tm = 1 << (2 - T);
        const bool act = lane & cm;
#pragma unroll
        for (int r = 0; r < 8; r++)
            if (!(r & tm)) {
                const int p = r | tm;
                const float r0 = act ? re[p] : re[r];
                const float r1 = act ? re[r] : re[p];
                const float i0 = act ? im[p] : im[r];
                const float i1 = act ? im[r] : im[p];
                re[r] = r0; re[p] = r1; im[r] = i0; im[p] = i1;
            }
    } else {
        constexpr int cm = 1 << (7 - C), tm = 1 << (7 - T);
        const int src = (lane & cm) ? (lane ^ tm) : lane;
#pragma unroll
        for (int r = 0; r < 8; r++) {
            re[r] = __shfl_sync(0xffffffffu, re[r], src);
            im[r] = __shfl_sync(0xffffffffu, im[r], src);
        }
    }
}

template <int L>
__device__ __forceinline__ void do_layer(float (&re)[8], float (&im)[8],
                                         const float* __restrict__ sp, int lane) {
#define ROTG(Q) {                                                                   \
        const float phi = sp[(L * 8 + Q) * 3 + 0];                                  \
        const float th  = sp[(L * 8 + Q) * 3 + 1];                                  \
        const float om  = sp[(L * 8 + Q) * 3 + 2];                                  \
        float s, c, sa, ca, sd, cd;                                                 \
        sincosf(0.5f * th, &s, &c);                                                 \
        sincosf(0.5f * (phi + om), &sa, &ca);                                       \
        sincosf(0.5f * (phi - om), &sd, &cd);                                       \
        rot_gate<Q>(re, im, ca * c, -sa * c, -cd * s, -sd * s,                      \
                    cd * s, -sd * s, ca * c, sa * c, lane); }
    ROTG(0) ROTG(1) ROTG(2) ROTG(3) ROTG(4) ROTG(5) ROTG(6) ROTG(7)
#undef ROTG
    cnot_gate<0, (0 + L + 1) % 8>(re, im, lane);
    cnot_gate<1, (1 + L + 1) % 8>(re, im, lane);
    cnot_gate<2, (2 + L + 1) % 8>(re, im, lane);
    cnot_gate<3, (3 + L + 1) % 8>(re, im, lane);
    cnot_gate<4, (4 + L + 1) % 8>(re, im, lane);
    cnot_gate<5, (5 + L + 1) % 8>(re, im, lane);
    cnot_gate<6, (6 + L + 1) % 8>(re, im, lane);
    cnot_gate<7, (7 + L + 1) % 8>(re, im, lane);
}

template <int Q>
__device__ __forceinline__ void measure(const float (&re)[8], const float (&im)[8], int lane,
                                        float& Z, float& X, float& Y) {
    float z = 0.0f, x = 0.0f, y = 0.0f;
    if constexpr (Q < 3) {
        constexpr int rm = 1 << (2 - Q);
#pragma unroll
        for (int r = 0; r < 8; r++) {
            const float ar = re[r], ai = im[r];
            const int p = r ^ rm;
            const float br = re[p], bi = im[p];
            const float sign = (r & rm) ? -1.0f : 1.0f;
            z += sign * (ar * ar + ai * ai);
            x += ar * br + ai * bi;
            y += sign * (ar * bi - ai * br);
        }
    } else {
        constexpr int lm = 1 << (7 - Q);
        const float sign = (lane & lm) ? -1.0f : 1.0f;
#pragma unroll
        for (int r = 0; r < 8; r++) {
            const float ar = re[r], ai = im[r];
            const float br = __shfl_xor_sync(0xffffffffu, ar, lm);
            const float bi = __shfl_xor_sync(0xffffffffu, ai, lm);
            z += sign * (ar * ar + ai * ai);
            x += ar * br + ai * bi;
            y += sign * (ar * bi - ai * br);
        }
    }
#pragma unroll
    for (int o = 16; o > 0; o >>= 1) {
        z += __shfl_xor_sync(0xffffffffu, z, o);
        x += __shfl_xor_sync(0xffffffffu, x, o);
        y += __shfl_xor_sync(0xffffffffu, y, o);
    }
    Z = z; X = x; Y = y;
}

__global__ void __launch_bounds__(256)
quantum_kernel(const float* __restrict__ enc, const float* __restrict__ params,
               __nv_bfloat16* __restrict__ mh, __nv_bfloat16* __restrict__ ml) {
    __shared__ float sp[144];
    __shared__ float sm[8][32];

    const int tid = threadIdx.x;
    const int lane = tid & 31, w = tid >> 5;
    if (tid < 144) sp[tid] = params[tid];
    __syncthreads();

    const int row = blockIdx.x * 8 + w;

    float re[8], im[8];
    float ss = 0.0f;
#pragma unroll
    for (int r = 0; r < 8; r++) {
        const float v = enc[(size_t)row * 256 + r * 32 + lane];
        re[r] = v; im[r] = 0.0f;
        ss += v * v;
    }
#pragma unroll
    for (int o = 16; o > 0; o >>= 1) ss += __shfl_xor_sync(0xffffffffu, ss, o);
    const float inv = 1.0f / fmaxf(sqrtf(ss), 1e-12f);
#pragma unroll
    for (int r = 0; r < 8; r++) re[r] *= inv;

    do_layer<0>(re, im, sp, lane);
    do_layer<1>(re, im, sp, lane);
    do_layer<2>(re, im, sp, lane);
    do_layer<3>(re, im, sp, lane);
    do_layer<4>(re, im, sp, lane);
    do_layer<5>(re, im, sp, lane);

#define MEAS(Q) {                                                   \
        float Z, X, Y;                                              \
        measure<Q>(re, im, lane, Z, X, Y);                          \
        if (lane == 0) { sm[w][Q] = Z; sm[w][8 + Q] = X; sm[w][16 + Q] = Y; } }
    MEAS(0) MEAS(1) MEAS(2) MEAS(3) MEAS(4) MEAS(5) MEAS(6) MEAS(7)
#undef MEAS
    __syncwarp();

    const float mv = (lane < 24) ? sm[w][lane] : 0.0f;
    const __nv_bfloat16 h = __float2bfloat16(mv);
    mh[(size_t)row * 32 + lane] = h;
    ml[(size_t)row * 32 + lane] = __float2bfloat16(mv - __bfloat162float(h));
}

// ---------------------------------------------------------------- launch
extern "C" void kernel_launch(void* const* d_in, const int* in_sizes, int n_in,
                              void* d_out, int out_size) {
    const float* x          = (const float*)d_in[0];
    const float* ew1        = (const float*)d_in[1];
    const float* eb1        = (const float*)d_in[2];
    const float* ew2        = (const float*)d_in[3];
    const float* eb2        = (const float*)d_in[4];
    const float* ew3        = (const float*)d_in[5];
    const float* eb3        = (const float*)d_in[6];
    const float* dec_params = (const float*)d_in[7];
    const float* dw1        = (const float*)d_in[8];
    const float* db1        = (const float*)d_in[9];
    const float* dw2        = (const float*)d_in[10];
    const float* db2        = (const float*)d_in[11];
    const float* dw3        = (const float*)d_in[12];
    const float* db3        = (const float*)d_in[13];
    const float* dw4        = (const float*)d_in[14];
    const float* db4        = (const float*)d_in[15];
    const float* dw5        = (const float*)d_in[16];
    const float* db5        = (const float*)d_in[17];
    float* out = (float*)d_out;

    __nv_bfloat16 *ah, *al, *wh, *wl;
    float* enc;
    cudaGetSymbolAddress((void**)&ah, g_act_h);
    cudaGetSymbolAddress((void**)&al, g_act_l);
    cudaGetSymbolAddress((void**)&wh, g_wt_h);
    cudaGetSymbolAddress((void**)&wl, g_wt_l);
    cudaGetSymbolAddress((void**)&enc, g_enc);

    cudaFuncSetAttribute(gemm_mma, cudaFuncAttributeMaxDynamicSharedMemorySize, GEMM_SMEM);

    // ---- conversions (2 launches) ----
    conv_x4<<<(BATCH * 2560) / 1024, 256>>>(x, ah + X_OFF, al + X_OFF);
    WTable wt;
    wt.s[0] = {ew1, W1_OFF, 1024, 2560};
    wt.s[1] = {ew2, W2_OFF, 512, 1024};
    wt.s[2] = {ew3, W3_OFF, 256, 512};
    wt.s[3] = {dw1, W4_OFF, 128, 24};
    wt.s[4] = {dw2, W5_OFF, 256, 128};
    wt.s[5] = {dw3, W6_OFF, 512, 256};
    wt.s[6] = {dw4, W7_OFF, 1024, 512};
    wt.s[7] = {dw5, W8_OFF, 2560, 1024};
    conv_w_all<<<WT_TOTAL / 256, 256>>>(wt, wh, wl);

    // ---- encoder ----
    gemm_mma<<<dim3(8, MBLOCKS), 256, GEMM_SMEM>>>(ah + X_OFF, al + X_OFF, wh + W1_OFF, wl + W1_OFF,
                                                   eb1, nullptr, ah + H1_OFF, al + H1_OFF, 1024, 2560, 1);
    gemm_mma<<<dim3(4, MBLOCKS), 256, GEMM_SMEM>>>(ah + H1_OFF, al + H1_OFF, wh + W2_OFF, wl + W2_OFF,
                                                   eb2, nullptr, ah + H2_OFF, al + H2_OFF, 512, 1024, 1);
    gemm_mma<<<dim3(2, MBLOCKS), 256, GEMM_SMEM>>>(ah + H2_OFF, al + H2_OFF, wh + W3_OFF, wl + W3_OFF,
                                                   eb3, enc, nullptr, nullptr, 256, 512, 2);

    // ---- quantum (one warp per row) ----
    quantum_kernel<<<BATCH / 8, 256>>>(enc, dec_params, ah + MS_OFF, al + MS_OFF);

    // ---- decoder ----
    gemm_mma<<<dim3(1, MBLOCKS), 256, GEMM_SMEM>>>(ah + MS_OFF, al + MS_OFF, wh + W4_OFF, wl + W4_OFF,
                                                   db1, nullptr, ah + D1_OFF, al + D1_OFF, 128, 32, 1);
    gemm_mma<<<dim3(2, MBLOCKS), 256, GEMM_SMEM>>>(ah + D1_OFF, al + D1_OFF, wh + W5_OFF, wl + W5_OFF,
                                                   db2, nullptr, ah + D2_OFF, al + D2_OFF, 256, 128, 1);
    gemm_mma<<<dim3(4, MBLOCKS), 256, GEMM_SMEM>>>(ah + D2_OFF, al + D2_OFF, wh + W6_OFF, wl + W6_OFF,
                                                   db3, nullptr, ah + D3_OFF, al + D3_OFF, 512, 256, 1);
    gemm_mma<<<dim3(8, MBLOCKS), 256, GEMM_SMEM>>>(ah + D3_OFF, al + D3_OFF, wh + W7_OFF, wl + W7_OFF,
                                                   db4, nullptr, ah + D4_OFF, al + D4_OFF, 1024, 512, 1);
    gemm_mma<<<dim3(20, MBLOCKS), 256, GEMM_SMEM>>>(ah + D4_OFF, al + D4_OFF, wh + W8_OFF, wl + W8_OFF,
                                                    db5, out, nullptr, nullptr, 2560, 1024, 2);
}